// round 7
// baseline (speedup 1.0000x reference)
#include <cuda_runtime.h>

#define SLEN 1024
#define BB   4
#define EMB  1024
#define NH   16
#define HD   64
#define MR   (SLEN*BB)   // 4096 rows

// ---------------- scratch (no allocation allowed) ----------------
__device__ float g_q[MR*EMB];
__device__ float g_k[MR*EMB];
__device__ float g_v[MR*EMB];
__device__ float g_ctx[MR*EMB];
__device__ float g_gate[BB*NH*SLEN];
__device__ float g_pb[NH*2048];          // [h][delta+1024], delta = k - q

// ---------------- generic 128x128x8 SGEMM: C = (A @ W^T + bias) * alpha ----
// A: (M,1024) row-major, W: (1024,1024) row-major (so we compute A·Wᵀ),
// C: (M,1024) row-major. Grid: (N/128, M/128). 256 threads, 8x8 micro-tile.
__device__ __forceinline__ void sgemm_body(const float* __restrict__ A,
                                           const float* __restrict__ W,
                                           const float* __restrict__ bias,
                                           float* __restrict__ C, float alpha)
{
    __shared__ float As[8][128];
    __shared__ float Ws[8][128];
    const int tid  = threadIdx.x;
    const int brow = blockIdx.y * 128;
    const int bcol = blockIdx.x * 128;
    const int lr   = tid >> 1;          // 0..127 (tile row to load)
    const int lc   = (tid & 1) << 2;    // 0 or 4 (k offset)
    const int trow = (tid >> 4) << 3;   // 0..120
    const int tcol = (tid & 15) << 3;   // 0..120

    float acc[8][8];
#pragma unroll
    for (int i = 0; i < 8; i++)
#pragma unroll
        for (int j = 0; j < 8; j++) acc[i][j] = 0.f;

    const float* Ap = A + (size_t)(brow + lr) * EMB + lc;
    const float* Wp = W + (size_t)(bcol + lr) * EMB + lc;

    for (int k0 = 0; k0 < EMB; k0 += 8) {
        float4 a = *(const float4*)(Ap + k0);
        float4 w = *(const float4*)(Wp + k0);
        As[lc+0][lr] = a.x; As[lc+1][lr] = a.y; As[lc+2][lr] = a.z; As[lc+3][lr] = a.w;
        Ws[lc+0][lr] = w.x; Ws[lc+1][lr] = w.y; Ws[lc+2][lr] = w.z; Ws[lc+3][lr] = w.w;
        __syncthreads();
#pragma unroll
        for (int kk = 0; kk < 8; kk++) {
            float4 a0 = *(const float4*)&As[kk][trow];
            float4 a1 = *(const float4*)&As[kk][trow+4];
            float4 w0 = *(const float4*)&Ws[kk][tcol];
            float4 w1 = *(const float4*)&Ws[kk][tcol+4];
            float ar[8] = {a0.x,a0.y,a0.z,a0.w,a1.x,a1.y,a1.z,a1.w};
            float wr[8] = {w0.x,w0.y,w0.z,w0.w,w1.x,w1.y,w1.z,w1.w};
#pragma unroll
            for (int i = 0; i < 8; i++)
#pragma unroll
                for (int j = 0; j < 8; j++)
                    acc[i][j] = fmaf(ar[i], wr[j], acc[i][j]);
        }
        __syncthreads();
    }

#pragma unroll
    for (int i = 0; i < 8; i++) {
        float* crow = C + (size_t)(brow + trow + i) * EMB + bcol + tcol;
#pragma unroll
        for (int j = 0; j < 8; j += 4) {
            float4 r;
            r.x = (acc[i][j+0] + bias[bcol+tcol+j+0]) * alpha;
            r.y = (acc[i][j+1] + bias[bcol+tcol+j+1]) * alpha;
            r.z = (acc[i][j+2] + bias[bcol+tcol+j+2]) * alpha;
            r.w = (acc[i][j+3] + bias[bcol+tcol+j+3]) * alpha;
            *(float4*)(crow + j) = r;
        }
    }
}

__global__ void __launch_bounds__(256, 2)
qkv_kernel(const float* __restrict__ query,
           const float* __restrict__ q_w, const float* __restrict__ q_b,
           const float* __restrict__ k_w, const float* __restrict__ k_b,
           const float* __restrict__ v_w, const float* __restrict__ v_b)
{
    const int z = blockIdx.z;
    if (z == 0)      sgemm_body(query, q_w, q_b, g_q, 0.125f);   // D^-0.5 = 0.125
    else if (z == 1) sgemm_body(query, k_w, k_b, g_k, 1.0f);
    else             sgemm_body(query, v_w, v_b, g_v, 1.0f);
}

__global__ void __launch_bounds__(256, 2)
outproj_kernel(const float* __restrict__ out_w, const float* __restrict__ out_b,
               float* __restrict__ out)
{
    sgemm_body(g_ctx, out_w, out_b, out, 1.0f);
}

// ---------------- relative position bias table ----------------
// bucket(rel = k - q), T5 bidirectional, NUM_BUCKETS=32, MAX_DISTANCE=128.
// Integer thresholds derived exactly from floor(log16(n/8)*8):
//   n: 8-11 -> 8, 12-15 -> 9, 16-22 -> 10, 23-31 -> 11,
//      32-45 -> 12, 46-63 -> 13, 64-90 -> 14, >=91 -> 15
__global__ void pbias_kernel(const float* __restrict__ rel_emb)
{
    int idx = blockIdx.x * blockDim.x + threadIdx.x;   // 0..2047
    if (idx >= 2048) return;
    if (idx == 0) {                                    // delta=-1024: never read
        for (int h = 0; h < NH; h++) g_pb[h*2048] = 0.f;
        return;
    }
    int rel = idx - 1024;                              // k - q
    int ret = (rel > 0) ? 16 : 0;
    int n   = rel < 0 ? -rel : rel;
    int bucket;
    if (n < 8) {
        bucket = ret + n;
    } else {
        int large;
        if      (n < 12) large = 8;
        else if (n < 16) large = 9;
        else if (n < 23) large = 10;
        else if (n < 32) large = 11;
        else if (n < 46) large = 12;
        else if (n < 64) large = 13;
        else if (n < 91) large = 14;
        else             large = 15;
        bucket = ret + large;
    }
    for (int h = 0; h < NH; h++)
        g_pb[h*2048 + idx] = rel_emb[bucket*NH + h];
}

// ---------------- GRU gate: gate[b,h,s] ----------------
__global__ void __launch_bounds__(256)
gate_kernel(const float* __restrict__ grep_w, const float* __restrict__ grep_b,
            const float* __restrict__ grep_a)
{
    __shared__ float w[8*64];
    __shared__ float wb[8];
    __shared__ float wa[16];
    const int tid = threadIdx.x;
    for (int i = tid; i < 512; i += 256) w[i] = grep_w[i];
    if (tid < 8)  wb[tid] = grep_b[tid];
    if (tid < 16) wa[tid] = grep_a[tid];
    __syncthreads();

    const int idx = blockIdx.x * 256 + tid;  // b*16384 + h*1024 + s
    const int s = idx & 1023;
    const int h = (idx >> 10) & 15;
    const int b = idx >> 14;

    const float* qv = g_q + ((size_t)s * BB + b) * EMB + h * HD;  // scaled q (matches ref)
    float acc[8] = {0.f,0.f,0.f,0.f,0.f,0.f,0.f,0.f};
#pragma unroll
    for (int d0 = 0; d0 < 64; d0 += 4) {
        float4 q4 = *(const float4*)(qv + d0);
        float qr[4] = {q4.x, q4.y, q4.z, q4.w};
#pragma unroll
        for (int e = 0; e < 8; e++) {
#pragma unroll
            for (int t = 0; t < 4; t++)
                acc[e] = fmaf(qr[t], w[e*64 + d0 + t], acc[e]);
        }
    }
    float sa = acc[0]+acc[1]+acc[2]+acc[3] + wb[0]+wb[1]+wb[2]+wb[3];
    float sb = acc[4]+acc[5]+acc[6]+acc[7] + wb[4]+wb[5]+wb[6]+wb[7];
    float ga = 1.f / (1.f + __expf(-sa));
    float gb = 1.f / (1.f + __expf(-sb));
    g_gate[idx] = ga * (gb * wa[h] - 1.0f) + 2.0f;
}

// ---------------- fused flash attention ----------------
// grid (S/64, B*H), 256 threads (16x16), q-tile 64 x k-tile 64, D=64.
// smem: Qt[d][q] (64x68), KPs: K as [d][k] (64x68) aliased with P as [k][q],
//       Vs[k][d] (64x64), pbs[2048], gsh[64]. Total 59648 B dynamic.
#define ATTN_SMEM ((2*64*68 + 64*64 + 2048 + 64) * 4)

__global__ void __launch_bounds__(256) attn_kernel()
{
    extern __shared__ float sm[];
    float* Qt  = sm;                  // [64][68] d-major
    float* KPs = sm + 64*68;          // K: [d][k] (68) ; later P: [k][q] (68)
    float* Vs  = sm + 2*64*68;        // [64][64] natural
    float* pbs = Vs + 64*64;          // [2048]
    float* gsh = pbs + 2048;          // [64]

    const int tid = threadIdx.x;
    const int tx  = tid & 15;         // k / d columns
    const int ty  = tid >> 4;         // q rows
    const int b   = blockIdx.y >> 4;
    const int h   = blockIdx.y & 15;
    const int qt  = blockIdx.x << 6;

    const int li = tid >> 2;          // 0..63 row to load
    const int lc = (tid & 3) << 2;    // 0,4,8,12

    // pbias table for this head (stays in smem for all 16 k-tiles)
    {
        const float* src = g_pb + h * 2048;
#pragma unroll
        for (int c = 0; c < 2; c++) {
            int o4 = (tid + c * 256) << 2;
            *(float4*)&pbs[o4] = *(const float4*)&src[o4];
        }
    }
    // Q tile, stored d-major (transposed)
    {
        const float* src = g_q + ((size_t)(qt + li) * BB + b) * EMB + h * HD;
#pragma unroll
        for (int c = 0; c < 4; c++) {
            int d0 = lc + (c << 4);
            float4 a = *(const float4*)(src + d0);
            Qt[(d0+0)*68 + li] = a.x;
            Qt[(d0+1)*68 + li] = a.y;
            Qt[(d0+2)*68 + li] = a.z;
            Qt[(d0+3)*68 + li] = a.w;
        }
    }
    if (tid < 64) gsh[tid] = g_gate[((b * NH + h) << 10) + qt + tid];
    __syncthreads();

    float gq[4];
#pragma unroll
    for (int i = 0; i < 4; i++) gq[i] = gsh[(ty << 2) + i];

    float o[4][4];
    float rm[4], rl[4];
#pragma unroll
    for (int i = 0; i < 4; i++) {
        rm[i] = -1e30f; rl[i] = 0.f;
#pragma unroll
        for (int j = 0; j < 4; j++) o[i][j] = 0.f;
    }

    for (int kt = 0; kt < SLEN; kt += 64) {
        // load K (d-major) and V (natural)
        {
            const size_t rb = ((size_t)(kt + li) * BB + b) * EMB + h * HD;
#pragma unroll
            for (int c = 0; c < 4; c++) {
                int d0 = lc + (c << 4);
                float4 a = *(const float4*)&g_k[rb + d0];
                KPs[(d0+0)*68 + li] = a.x;
                KPs[(d0+1)*68 + li] = a.y;
                KPs[(d0+2)*68 + li] = a.z;
                KPs[(d0+3)*68 + li] = a.w;
                *(float4*)&Vs[(li << 6) + d0] = *(const float4*)&g_v[rb + d0];
            }
        }
        __syncthreads();

        // S = Q · Kᵀ  (thread owns q = 4ty+i, k = 4tx+j)
        float scv[4][4];
#pragma unroll
        for (int i = 0; i < 4; i++)
#pragma unroll
            for (int j = 0; j < 4; j++) scv[i][j] = 0.f;

#pragma unroll 8
        for (int d = 0; d < 64; d++) {
            float4 q4 = *(const float4*)&Qt[d*68 + (ty << 2)];   // broadcast
            float4 k4 = *(const float4*)&KPs[d*68 + (tx << 2)];  // conflict-free
            float qr[4] = {q4.x, q4.y, q4.z, q4.w};
            float kr[4] = {k4.x, k4.y, k4.z, k4.w};
#pragma unroll
            for (int i = 0; i < 4; i++)
#pragma unroll
                for (int j = 0; j < 4; j++)
                    scv[i][j] = fmaf(qr[i], kr[j], scv[i][j]);
        }

        // + gate[q] * pbias[h][k - q + 1024]
        const int dbase = kt - qt + 1024 + (tx << 2) - (ty << 2);
#pragma unroll
        for (int i = 0; i < 4; i++)
#pragma unroll
            for (int j = 0; j < 4; j++)
                scv[i][j] = fmaf(gq[i], pbs[dbase + j - i], scv[i][j]);

        // online softmax (row reduction over 16 tx-threads = 16-lane half-warp)
#pragma unroll
        for (int i = 0; i < 4; i++) {
            float tm = fmaxf(fmaxf(scv[i][0], scv[i][1]), fmaxf(scv[i][2], scv[i][3]));
#pragma unroll
            for (int off = 8; off > 0; off >>= 1)
                tm = fmaxf(tm, __shfl_xor_sync(0xffffffffu, tm, off));
            float nm   = fmaxf(rm[i], tm);
            float corr = __expf(rm[i] - nm);
            rm[i] = nm;
            float ts = 0.f;
#pragma unroll
            for (int j = 0; j < 4; j++) {
                scv[i][j] = __expf(scv[i][j] - nm);
                ts += scv[i][j];
            }
#pragma unroll
            for (int off = 8; off > 0; off >>= 1)
                ts += __shfl_xor_sync(0xffffffffu, ts, off);
            rl[i] = rl[i] * corr + ts;
#pragma unroll
            for (int j = 0; j < 4; j++) o[i][j] *= corr;
        }
        __syncthreads();                 // everyone done reading K from KPs

        // store P as [k][q] into KPs (aliases K, now dead)
#pragma unroll
        for (int j = 0; j < 4; j++) {
            float4 pv = make_float4(scv[0][j], scv[1][j], scv[2][j], scv[3][j]);
            *(float4*)&KPs[((tx << 2) + j)*68 + (ty << 2)] = pv;
        }
        __syncthreads();

        // O += P · V  (thread owns q = 4ty+i, d = 4tx+j)
#pragma unroll 8
        for (int kk = 0; kk < 64; kk++) {
            float4 p4 = *(const float4*)&KPs[kk*68 + (ty << 2)];   // broadcast
            float4 v4 = *(const float4*)&Vs[(kk << 6) + (tx << 2)];// conflict-free
            float pr[4] = {p4.x, p4.y, p4.z, p4.w};
            float vr[4] = {v4.x, v4.y, v4.z, v4.w};
#pragma unroll
            for (int i = 0; i < 4; i++)
#pragma unroll
                for (int j = 0; j < 4; j++)
                    o[i][j] = fmaf(pr[i], vr[j], o[i][j]);
        }
        __syncthreads();                 // before next tile overwrites KPs/Vs
    }

    // normalize + write ctx in (S,B,E) layout: row (q,b), col h*64+d
#pragma unroll
    for (int i = 0; i < 4; i++) {
        float inv = 1.f / rl[i];
        float4 r = make_float4(o[i][0]*inv, o[i][1]*inv, o[i][2]*inv, o[i][3]*inv);
        float* dst = g_ctx + ((size_t)(qt + (ty << 2) + i) * BB + b) * EMB
                     + h * HD + (tx << 2);
        *(float4*)dst = r;
    }
}

// ---------------- launcher ----------------
extern "C" void kernel_launch(void* const* d_in, const int* in_sizes, int n_in,
                              void* d_out, int out_size)
{
    const float* query  = (const float*)d_in[0];
    const float* q_w    = (const float*)d_in[1];
    const float* q_b    = (const float*)d_in[2];
    const float* k_w    = (const float*)d_in[3];
    const float* k_b    = (const float*)d_in[4];
    const float* v_w    = (const float*)d_in[5];
    const float* v_b    = (const float*)d_in[6];
    const float* out_w  = (const float*)d_in[7];
    const float* out_b  = (const float*)d_in[8];
    const float* rel    = (const float*)d_in[9];
    const float* grep_w = (const float*)d_in[10];
    const float* grep_b = (const float*)d_in[11];
    const float* grep_a = (const float*)d_in[12];
    float* out = (float*)d_out;

    cudaFuncSetAttribute(attn_kernel, cudaFuncAttributeMaxDynamicSharedMemorySize,
                         ATTN_SMEM);

    // Q/K/V projections (z selects which)
    qkv_kernel<<<dim3(EMB/128, MR/128, 3), 256>>>(query, q_w, q_b, k_w, k_b, v_w, v_b);
    // position-bias table and gates (gate needs g_q — same stream ordering)
    pbias_kernel<<<8, 256>>>(rel);
    gate_kernel<<<(BB*NH*SLEN)/256, 256>>>(grep_w, grep_b, grep_a);
    // fused attention
    attn_kernel<<<dim3(SLEN/64, BB*NH), 256, ATTN_SMEM>>>();
    // output projection
    outproj_kernel<<<dim3(EMB/128, MR/128), 256>>>(out_w, out_b, out);
}

// round 8
// speedup vs baseline: 1.8993x; 1.8993x over previous
#include <cuda_runtime.h>

#define SLEN 1024
#define BB   4
#define EMB  1024
#define NH   16
#define HD   64
#define MR   (SLEN*BB)   // 4096 rows

// ---------------- scratch (no allocation allowed) ----------------
__device__ float g_q[MR*EMB];
__device__ float g_k[MR*EMB];
__device__ float g_v[MR*EMB];
__device__ float g_ctx[MR*EMB];
__device__ float g_gate[BB*NH*SLEN];
__device__ float g_pb[NH*2048];          // [h][delta+1024], delta = k - q

// ================= tf32 tensor-core GEMM: C = (A @ W^T + bias) * alpha ====
// A: (M,1024) row-major, W: (1024,1024) row-major, C: (M,1024) row-major.
// CTA tile 128x128x32, 8 warps in 2(M)x4(N), warp tile 64x32 via m16n8k8.
// smem row stride 36 => fragment load bank = (4g+t+const)%32, conflict-free.
#define GS        (128*36)            // unsigned per buffer
#define GEMM_SMEM (4*GS*4)            // 2 bufs x (A+B) = 73728 bytes

__device__ __forceinline__ unsigned f2tf(float x) {
    unsigned r; asm("cvt.rna.tf32.f32 %0, %1;" : "=r"(r) : "f"(x)); return r;
}

__device__ __forceinline__ void mma_tf32(float c[4], const unsigned a[4],
                                         const unsigned b[2]) {
    asm volatile(
        "mma.sync.aligned.m16n8k8.row.col.f32.tf32.tf32.f32 "
        "{%0,%1,%2,%3}, {%4,%5,%6,%7}, {%8,%9}, {%0,%1,%2,%3};"
        : "+f"(c[0]), "+f"(c[1]), "+f"(c[2]), "+f"(c[3])
        : "r"(a[0]), "r"(a[1]), "r"(a[2]), "r"(a[3]), "r"(b[0]), "r"(b[1]));
}

__device__ __forceinline__ void tgemm_body(const float* __restrict__ A,
                                           const float* __restrict__ W,
                                           const float* __restrict__ bias,
                                           float* __restrict__ C, float alpha)
{
    extern __shared__ unsigned smu[];
    unsigned* As = smu;               // [2][128][36]
    unsigned* Bs = smu + 2*GS;        // [2][128][36]

    const int tid  = threadIdx.x;
    const int brow = blockIdx.y * 128;
    const int bcol = blockIdx.x * 128;
    const int lr   = tid >> 3;        // 0..31 (tile row group)
    const int lc   = (tid & 7) << 2;  // 0,4,...,28 (k offset)

    const int lane = tid & 31;
    const int wid  = tid >> 5;
    const int wm   = (wid >> 2) << 6; // 0 or 64
    const int wn   = (wid & 3) << 5;  // 0,32,64,96
    const int g    = lane >> 2;       // 0..7
    const int t    = lane & 3;        // 0..3

    float c[4][4][4];
#pragma unroll
    for (int im = 0; im < 4; im++)
#pragma unroll
        for (int jn = 0; jn < 4; jn++)
#pragma unroll
            for (int r = 0; r < 4; r++) c[im][jn][r] = 0.f;

    const float* Ab = A + (size_t)(brow + lr) * EMB + lc;
    const float* Wb = W + (size_t)(bcol + lr) * EMB + lc;

    float4 ra[4], rw[4];
#pragma unroll
    for (int i = 0; i < 4; i++) {
        ra[i] = *(const float4*)(Ab + (size_t)i * 32 * EMB);
        rw[i] = *(const float4*)(Wb + (size_t)i * 32 * EMB);
    }
#pragma unroll
    for (int i = 0; i < 4; i++) {
        unsigned* pa = &As[(lr + 32*i)*36 + lc];
        pa[0]=f2tf(ra[i].x); pa[1]=f2tf(ra[i].y); pa[2]=f2tf(ra[i].z); pa[3]=f2tf(ra[i].w);
        unsigned* pb = &Bs[(lr + 32*i)*36 + lc];
        pb[0]=f2tf(rw[i].x); pb[1]=f2tf(rw[i].y); pb[2]=f2tf(rw[i].z); pb[3]=f2tf(rw[i].w);
    }
    __syncthreads();

    int buf = 0;
    for (int kt = 0; kt < EMB; kt += 32) {
        if (kt + 32 < EMB) {
#pragma unroll
            for (int i = 0; i < 4; i++) {
                ra[i] = *(const float4*)(Ab + kt + 32 + (size_t)i * 32 * EMB);
                rw[i] = *(const float4*)(Wb + kt + 32 + (size_t)i * 32 * EMB);
            }
        }
        const unsigned* Ac = As + buf*GS;
        const unsigned* Bc = Bs + buf*GS;
#pragma unroll
        for (int ks = 0; ks < 32; ks += 8) {
            unsigned a[4][4], b[4][2];
#pragma unroll
            for (int im = 0; im < 4; im++) {
                int m0 = wm + im*16;
                a[im][0] = Ac[(m0 + g    )*36 + ks + t];
                a[im][1] = Ac[(m0 + 8 + g)*36 + ks + t];
                a[im][2] = Ac[(m0 + g    )*36 + ks + t + 4];
                a[im][3] = Ac[(m0 + 8 + g)*36 + ks + t + 4];
            }
#pragma unroll
            for (int jn = 0; jn < 4; jn++) {
                int n0 = wn + jn*8;
                b[jn][0] = Bc[(n0 + g)*36 + ks + t];
                b[jn][1] = Bc[(n0 + g)*36 + ks + t + 4];
            }
#pragma unroll
            for (int im = 0; im < 4; im++)
#pragma unroll
                for (int jn = 0; jn < 4; jn++)
                    mma_tf32(c[im][jn], a[im], b[jn]);
        }
        if (kt + 32 < EMB) {
            unsigned* Aw = As + (buf^1)*GS;
            unsigned* Bw = Bs + (buf^1)*GS;
#pragma unroll
            for (int i = 0; i < 4; i++) {
                unsigned* pa = &Aw[(lr + 32*i)*36 + lc];
                pa[0]=f2tf(ra[i].x); pa[1]=f2tf(ra[i].y); pa[2]=f2tf(ra[i].z); pa[3]=f2tf(ra[i].w);
                unsigned* pb = &Bw[(lr + 32*i)*36 + lc];
                pb[0]=f2tf(rw[i].x); pb[1]=f2tf(rw[i].y); pb[2]=f2tf(rw[i].z); pb[3]=f2tf(rw[i].w);
            }
            __syncthreads();
            buf ^= 1;
        }
    }

    // epilogue: c0,c1 -> row g, cols 2t,2t+1 ; c2,c3 -> row g+8
#pragma unroll
    for (int im = 0; im < 4; im++) {
        int row0 = brow + wm + im*16 + g;
#pragma unroll
        for (int jn = 0; jn < 4; jn++) {
            int col = bcol + wn + jn*8 + 2*t;
            float bx = bias[col], by = bias[col + 1];
            float2 r0 = make_float2((c[im][jn][0] + bx) * alpha,
                                    (c[im][jn][1] + by) * alpha);
            float2 r1 = make_float2((c[im][jn][2] + bx) * alpha,
                                    (c[im][jn][3] + by) * alpha);
            *(float2*)&C[(size_t)row0 * EMB + col]       = r0;
            *(float2*)&C[(size_t)(row0 + 8) * EMB + col] = r1;
        }
    }
}

__global__ void __launch_bounds__(256)
qkv_kernel(const float* __restrict__ query,
           const float* __restrict__ q_w, const float* __restrict__ q_b,
           const float* __restrict__ k_w, const float* __restrict__ k_b,
           const float* __restrict__ v_w, const float* __restrict__ v_b)
{
    const int z = blockIdx.z;
    if (z == 0)      tgemm_body(query, q_w, q_b, g_q, 0.125f);   // D^-0.5
    else if (z == 1) tgemm_body(query, k_w, k_b, g_k, 1.0f);
    else             tgemm_body(query, v_w, v_b, g_v, 1.0f);
}

__global__ void __launch_bounds__(256)
outproj_kernel(const float* __restrict__ out_w, const float* __restrict__ out_b,
               float* __restrict__ out)
{
    tgemm_body(g_ctx, out_w, out_b, out, 1.0f);
}

// ---------------- relative position bias table ----------------
__global__ void pbias_kernel(const float* __restrict__ rel_emb)
{
    int idx = blockIdx.x * blockDim.x + threadIdx.x;   // 0..2047
    if (idx >= 2048) return;
    if (idx == 0) {                                    // delta=-1024: never read
        for (int h = 0; h < NH; h++) g_pb[h*2048] = 0.f;
        return;
    }
    int rel = idx - 1024;                              // k - q
    int ret = (rel > 0) ? 16 : 0;
    int n   = rel < 0 ? -rel : rel;
    int bucket;
    if (n < 8) {
        bucket = ret + n;
    } else {
        int large;
        if      (n < 12) large = 8;
        else if (n < 16) large = 9;
        else if (n < 23) large = 10;
        else if (n < 32) large = 11;
        else if (n < 46) large = 12;
        else if (n < 64) large = 13;
        else if (n < 91) large = 14;
        else             large = 15;
        bucket = ret + large;
    }
    for (int h = 0; h < NH; h++)
        g_pb[h*2048 + idx] = rel_emb[bucket*NH + h];
}

// ---------------- GRU gate: gate[b,h,s] ----------------
__global__ void __launch_bounds__(256)
gate_kernel(const float* __restrict__ grep_w, const float* __restrict__ grep_b,
            const float* __restrict__ grep_a)
{
    __shared__ float w[8*64];
    __shared__ float wb[8];
    __shared__ float wa[16];
    const int tid = threadIdx.x;
    for (int i = tid; i < 512; i += 256) w[i] = grep_w[i];
    if (tid < 8)  wb[tid] = grep_b[tid];
    if (tid < 16) wa[tid] = grep_a[tid];
    __syncthreads();

    const int idx = blockIdx.x * 256 + tid;  // b*16384 + h*1024 + s
    const int s = idx & 1023;
    const int h = (idx >> 10) & 15;
    const int b = idx >> 14;

    const float* qv = g_q + ((size_t)s * BB + b) * EMB + h * HD;
    float acc[8] = {0.f,0.f,0.f,0.f,0.f,0.f,0.f,0.f};
#pragma unroll
    for (int d0 = 0; d0 < 64; d0 += 4) {
        float4 q4 = *(const float4*)(qv + d0);
        float qr[4] = {q4.x, q4.y, q4.z, q4.w};
#pragma unroll
        for (int e = 0; e < 8; e++) {
#pragma unroll
            for (int t = 0; t < 4; t++)
                acc[e] = fmaf(qr[t], w[e*64 + d0 + t], acc[e]);
        }
    }
    float sa = acc[0]+acc[1]+acc[2]+acc[3] + wb[0]+wb[1]+wb[2]+wb[3];
    float sb = acc[4]+acc[5]+acc[6]+acc[7] + wb[4]+wb[5]+wb[6]+wb[7];
    float ga = 1.f / (1.f + __expf(-sa));
    float gb = 1.f / (1.f + __expf(-sb));
    g_gate[idx] = ga * (gb * wa[h] - 1.0f) + 2.0f;
}

// ---------------- fused flash attention (unchanged from R6) ----------------
#define ATTN_SMEM ((2*64*68 + 64*64 + 2048 + 64) * 4)

__global__ void __launch_bounds__(256) attn_kernel()
{
    extern __shared__ float sm[];
    float* Qt  = sm;                  // [64][68] d-major
    float* KPs = sm + 64*68;          // K: [d][k] (68) ; later P: [k][q] (68)
    float* Vs  = sm + 2*64*68;        // [64][64] natural
    float* pbs = Vs + 64*64;          // [2048]
    float* gsh = pbs + 2048;          // [64]

    const int tid = threadIdx.x;
    const int tx  = tid & 15;
    const int ty  = tid >> 4;
    const int b   = blockIdx.y >> 4;
    const int h   = blockIdx.y & 15;
    const int qt  = blockIdx.x << 6;

    const int li = tid >> 2;
    const int lc = (tid & 3) << 2;

    {
        const float* src = g_pb + h * 2048;
#pragma unroll
        for (int c = 0; c < 2; c++) {
            int o4 = (tid + c * 256) << 2;
            *(float4*)&pbs[o4] = *(const float4*)&src[o4];
        }
    }
    {
        const float* src = g_q + ((size_t)(qt + li) * BB + b) * EMB + h * HD;
#pragma unroll
        for (int c = 0; c < 4; c++) {
            int d0 = lc + (c << 4);
            float4 a = *(const float4*)(src + d0);
            Qt[(d0+0)*68 + li] = a.x;
            Qt[(d0+1)*68 + li] = a.y;
            Qt[(d0+2)*68 + li] = a.z;
            Qt[(d0+3)*68 + li] = a.w;
        }
    }
    if (tid < 64) gsh[tid] = g_gate[((b * NH + h) << 10) + qt + tid];
    __syncthreads();

    float gq[4];
#pragma unroll
    for (int i = 0; i < 4; i++) gq[i] = gsh[(ty << 2) + i];

    float o[4][4];
    float rm[4], rl[4];
#pragma unroll
    for (int i = 0; i < 4; i++) {
        rm[i] = -1e30f; rl[i] = 0.f;
#pragma unroll
        for (int j = 0; j < 4; j++) o[i][j] = 0.f;
    }

    for (int kt = 0; kt < SLEN; kt += 64) {
        {
            const size_t rb = ((size_t)(kt + li) * BB + b) * EMB + h * HD;
#pragma unroll
            for (int c = 0; c < 4; c++) {
                int d0 = lc + (c << 4);
                float4 a = *(const float4*)&g_k[rb + d0];
                KPs[(d0+0)*68 + li] = a.x;
                KPs[(d0+1)*68 + li] = a.y;
                KPs[(d0+2)*68 + li] = a.z;
                KPs[(d0+3)*68 + li] = a.w;
                *(float4*)&Vs[(li << 6) + d0] = *(const float4*)&g_v[rb + d0];
            }
        }
        __syncthreads();

        float scv[4][4];
#pragma unroll
        for (int i = 0; i < 4; i++)
#pragma unroll
            for (int j = 0; j < 4; j++) scv[i][j] = 0.f;

#pragma unroll 8
        for (int d = 0; d < 64; d++) {
            float4 q4 = *(const float4*)&Qt[d*68 + (ty << 2)];
            float4 k4 = *(const float4*)&KPs[d*68 + (tx << 2)];
            float qr[4] = {q4.x, q4.y, q4.z, q4.w};
            float kr[4] = {k4.x, k4.y, k4.z, k4.w};
#pragma unroll
            for (int i = 0; i < 4; i++)
#pragma unroll
                for (int j = 0; j < 4; j++)
                    scv[i][j] = fmaf(qr[i], kr[j], scv[i][j]);
        }

        const int dbase = kt - qt + 1024 + (tx << 2) - (ty << 2);
#pragma unroll
        for (int i = 0; i < 4; i++)
#pragma unroll
            for (int j = 0; j < 4; j++)
                scv[i][j] = fmaf(gq[i], pbs[dbase + j - i], scv[i][j]);

#pragma unroll
        for (int i = 0; i < 4; i++) {
            float tm = fmaxf(fmaxf(scv[i][0], scv[i][1]), fmaxf(scv[i][2], scv[i][3]));
#pragma unroll
            for (int off = 8; off > 0; off >>= 1)
                tm = fmaxf(tm, __shfl_xor_sync(0xffffffffu, tm, off));
            float nm   = fmaxf(rm[i], tm);
            float corr = __expf(rm[i] - nm);
            rm[i] = nm;
            float ts = 0.f;
#pragma unroll
            for (int j = 0; j < 4; j++) {
                scv[i][j] = __expf(scv[i][j] - nm);
                ts += scv[i][j];
            }
#pragma unroll
            for (int off = 8; off > 0; off >>= 1)
                ts += __shfl_xor_sync(0xffffffffu, ts, off);
            rl[i] = rl[i] * corr + ts;
#pragma unroll
            for (int j = 0; j < 4; j++) o[i][j] *= corr;
        }
        __syncthreads();

#pragma unroll
        for (int j = 0; j < 4; j++) {
            float4 pv = make_float4(scv[0][j], scv[1][j], scv[2][j], scv[3][j]);
            *(float4*)&KPs[((tx << 2) + j)*68 + (ty << 2)] = pv;
        }
        __syncthreads();

#pragma unroll 8
        for (int kk = 0; kk < 64; kk++) {
            float4 p4 = *(const float4*)&KPs[kk*68 + (ty << 2)];
            float4 v4 = *(const float4*)&Vs[(kk << 6) + (tx << 2)];
            float pr[4] = {p4.x, p4.y, p4.z, p4.w};
            float vr[4] = {v4.x, v4.y, v4.z, v4.w};
#pragma unroll
            for (int i = 0; i < 4; i++)
#pragma unroll
                for (int j = 0; j < 4; j++)
                    o[i][j] = fmaf(pr[i], vr[j], o[i][j]);
        }
        __syncthreads();
    }

#pragma unroll
    for (int i = 0; i < 4; i++) {
        float inv = 1.f / rl[i];
        float4 r = make_float4(o[i][0]*inv, o[i][1]*inv, o[i][2]*inv, o[i][3]*inv);
        float* dst = g_ctx + ((size_t)(qt + (ty << 2) + i) * BB + b) * EMB
                     + h * HD + (tx << 2);
        *(float4*)dst = r;
    }
}

// ---------------- launcher ----------------
extern "C" void kernel_launch(void* const* d_in, const int* in_sizes, int n_in,
                              void* d_out, int out_size)
{
    const float* query  = (const float*)d_in[0];
    const float* q_w    = (const float*)d_in[1];
    const float* q_b    = (const float*)d_in[2];
    const float* k_w    = (const float*)d_in[3];
    const float* k_b    = (const float*)d_in[4];
    const float* v_w    = (const float*)d_in[5];
    const float* v_b    = (const float*)d_in[6];
    const float* out_w  = (const float*)d_in[7];
    const float* out_b  = (const float*)d_in[8];
    const float* rel    = (const float*)d_in[9];
    const float* grep_w = (const float*)d_in[10];
    const float* grep_b = (const float*)d_in[11];
    const float* grep_a = (const float*)d_in[12];
    float* out = (float*)d_out;

    cudaFuncSetAttribute(attn_kernel, cudaFuncAttributeMaxDynamicSharedMemorySize,
                         ATTN_SMEM);
    cudaFuncSetAttribute(qkv_kernel, cudaFuncAttributeMaxDynamicSharedMemorySize,
                         GEMM_SMEM);
    cudaFuncSetAttribute(outproj_kernel, cudaFuncAttributeMaxDynamicSharedMemorySize,
                         GEMM_SMEM);

    // Q/K/V projections (z selects which) — tf32 tensor-core GEMM
    qkv_kernel<<<dim3(EMB/128, MR/128, 3), 256, GEMM_SMEM>>>(
        query, q_w, q_b, k_w, k_b, v_w, v_b);
    // position-bias table and gates
    pbias_kernel<<<8, 256>>>(rel);
    gate_kernel<<<(BB*NH*SLEN)/256, 256>>>(grep_w, grep_b, grep_a);
    // fused attention
    attn_kernel<<<dim3(SLEN/64, BB*NH), 256, ATTN_SMEM>>>();
    // output projection
    outproj_kernel<<<dim3(EMB/128, MR/128), 256, GEMM_SMEM>>>(out_w, out_b, out);
}